// round 10
// baseline (speedup 1.0000x reference)
#include <cuda_runtime.h>

// ---------------------------------------------------------------------------
// NCC plane-sweep forward (B=1, N=4, H=160, W=192, patch 5x5, 9 depth taps,
// depth dilation 2). R9 = R8 with ONE change:
//   PP = K·R precompute now FMA-ascending (standalone einsum -> cuBLAS GEMM),
//   while the fused Hmat chain stays mul+add (in-fusion decomposed dots) and
//   the tap matvec stays FMA (surviving dot_general).
// ---------------------------------------------------------------------------

namespace cfg {
constexpr int H = 160;
constexpr int W = 192;
constexpr int NVIEW = 4;
constexpr int DS = 9;
constexpr int DIL = 2;
constexpr int PS = 25;
constexpr int HW = H * W;
constexpr float THR = 0.5f;
}

__device__ float g_PP[cfg::NVIEW][9];    // K * R
__device__ float g_K0[cfg::NVIEW][9];    // K^-1 (Ks[:, :, 0])
__device__ float g_T[cfg::NVIEW][3];
__device__ float g_score[cfg::DS * cfg::HW];
__device__ unsigned char g_many[cfg::DS * cfg::HW];

__device__ __forceinline__ int perm_d(int d) {
    return (d == 0) ? 4 : (d == 4) ? 0 : d;
}

// Plain mul+add sequential chain (no FMA): ((a0b0 + a1b1) + a2b2)
__device__ __forceinline__ float dot3m(float a0, float b0, float a1, float b1,
                                       float a2, float b2) {
    return __fadd_rn(__fadd_rn(__fmul_rn(a0, b0), __fmul_rn(a1, b1)),
                     __fmul_rn(a2, b2));
}

// Ascending FMA chain, zero init (cuBLAS / llvm.fmuladd dot lowering)
__device__ __forceinline__ float dot3f(float a0, float b0, float a1, float b1,
                                       float a2, float b2) {
    return fmaf(a2, b2, fmaf(a1, b1, __fmul_rn(a0, b0)));
}

// ---------------------------------------------------------------------------
__global__ void precompute_kernel(const float* __restrict__ Ks,
                                  const float* __restrict__ Rs,
                                  const float* __restrict__ Ts) {
    int n = threadIdx.x;
    if (n >= cfg::NVIEW) return;
    const float* Ki = Ks + n * 18;       // Ks[0,n,0] = K^-1
    const float* K  = Ks + n * 18 + 9;   // Ks[0,n,1] = K
    const float* R  = Rs + n * 9;
#pragma unroll
    for (int i = 0; i < 3; i++)
#pragma unroll
        for (int j = 0; j < 3; j++)
            g_PP[n][i * 3 + j] = dot3f(K[i * 3 + 0], R[0 * 3 + j],   // R9: FMA
                                       K[i * 3 + 1], R[1 * 3 + j],
                                       K[i * 3 + 2], R[2 * 3 + j]);
#pragma unroll
    for (int i = 0; i < 9; i++) g_K0[n][i] = Ki[i];
#pragma unroll
    for (int i = 0; i < 3; i++) g_T[n][i] = Ts[n * 3 + i];
}

// ---------------------------------------------------------------------------
__global__ void __launch_bounds__(128)
ncc_score_kernel(const float* __restrict__ src,
                 const float* __restrict__ dst,
                 const float* __restrict__ depth,
                 const float* __restrict__ norm) {
    using namespace cfg;
    int idx = blockIdx.x * blockDim.x + threadIdx.x;
    if (idx >= DS * HW) return;
    int d   = idx / HW;
    int pix = idx - d * HW;
    int h   = pix / W;
    int w   = pix - h * W;

    int pd = perm_d(d);
    int pi = pd / 3 - 1;
    int pj = pd % 3 - 1;

    // dilated depth tap (zero-padded)
    int hd = h + DIL * pi, wd = w + DIL * pj;
    float dp = 0.f;
    if (hd >= 0 && hd < H && wd >= 0 && wd < W) dp = depth[hd * W + wd];

    // normal tap (dilation 1, zero-padded)
    int hn = h + pi, wn = w + pj;
    float nv0 = 0.f, nv1 = 0.f, nv2 = 0.f;
    if (hn >= 0 && hn < H && wn >= 0 && wn < W) {
        int o = hn * W + wn;
        nv0 = norm[o];
        nv1 = norm[HW + o];
        nv2 = norm[2 * HW + o];
    }
    float dsafe = (dp != 0.f) ? dp : 1.f;
    bool valid_dn = (dp > 0.f) && (nv2 < 0.f);

    // src patch (zero-padded): mean, then center  (mul+add score path)
    float sp[PS];
    unsigned inb = 0u;
    float ssum = 0.f;
#pragma unroll
    for (int i = 0; i < 5; i++) {
#pragma unroll
        for (int j = 0; j < 5; j++) {
            int p = i * 5 + j;
            int hh = h + i - 2, ww = w + j - 2;
            float v = 0.f;
            if (hh >= 0 && hh < H && ww >= 0 && ww < W) {
                v = src[hh * W + ww];
                inb |= (1u << p);
            }
            sp[p] = v;
            ssum = __fadd_rn(ssum, v);
        }
    }
    float smean = __fdiv_rn(ssum, 25.f);
    float sc[PS];
    float svar = 0.f;
#pragma unroll
    for (int p = 0; p < PS; p++) {
        sc[p] = __fsub_rn(sp[p], smean);
        svar = __fadd_rn(svar, __fmul_rn(sc[p], sc[p]));
    }
    svar = __fdiv_rn(svar, 25.f);

    float fw = (float)w, fh = (float)h;
    float vscore[NVIEW];
    bool many = false;

#pragma unroll
    for (int n = 0; n < NVIEW; n++) {
        // m = I - (T_i * n_j) / dsafe  (entry-wise IEEE ops)
        float mM[9];
#pragma unroll
        for (int i = 0; i < 3; i++) {
            float Ti = g_T[n][i];
            float q0 = __fdiv_rn(__fmul_rn(Ti, nv0), dsafe);
            float q1 = __fdiv_rn(__fmul_rn(Ti, nv1), dsafe);
            float q2 = __fdiv_rn(__fmul_rn(Ti, nv2), dsafe);
            mM[i * 3 + 0] = __fsub_rn((i == 0) ? 1.f : 0.f, q0);
            mM[i * 3 + 1] = __fsub_rn((i == 1) ? 1.f : 0.f, q1);
            mM[i * 3 + 2] = __fsub_rn((i == 2) ? 1.f : 0.f, q2);
        }
        // tmp = PP @ m ; Hm = tmp @ K0  (mul+add chains, L-assoc)
        float tmp[9], Hm[9];
#pragma unroll
        for (int i = 0; i < 3; i++)
#pragma unroll
            for (int k = 0; k < 3; k++)
                tmp[i * 3 + k] = dot3m(g_PP[n][i * 3 + 0], mM[0 * 3 + k],
                                       g_PP[n][i * 3 + 1], mM[1 * 3 + k],
                                       g_PP[n][i * 3 + 2], mM[2 * 3 + k]);
#pragma unroll
        for (int i = 0; i < 3; i++)
#pragma unroll
            for (int l = 0; l < 3; l++)
                Hm[i * 3 + l] = dot3m(tmp[i * 3 + 0], g_K0[n][0 * 3 + l],
                                      tmp[i * 3 + 1], g_K0[n][1 * 3 + l],
                                      tmp[i * 3 + 2], g_K0[n][2 * 3 + l]);

        const float* dstn = dst + n * HW;
        float samp[PS];
        bool mall = valid_dn;
        float dsum = 0.f;

#pragma unroll
        for (int i = 0; i < 5; i++) {
            float cy = fh + (float)(i - 2);
#pragma unroll
            for (int j = 0; j < 5; j++) {
                int p = i * 5 + j;
                float cx = fw + (float)(j - 2);
                // tap matvec: ascending-FMA (surviving dot_general)
                float X0 = dot3f(Hm[0], cx, Hm[1], cy, Hm[2], 1.f);
                float X1 = dot3f(Hm[3], cx, Hm[4], cy, Hm[5], 1.f);
                float z  = dot3f(Hm[6], cx, Hm[7], cy, Hm[8], 1.f);
                float zs = (z != 0.f) ? z : 1.f;
                float xw = __fdiv_rn(X0, zs);
                float yw = __fdiv_rn(X1, zs);
                bool ok = valid_dn && ((inb >> p) & 1u) && (z > 0.f) &&
                          (xw > 0.f) && (xw < (float)(W - 1)) &&
                          (yw > 0.f) && (yw < (float)(H - 1));
                float s = 0.f;
                if (ok) s = dstn[(int)yw * W + (int)xw];
                samp[p] = s;
                mall = mall && ok;
                dsum = __fadd_rn(dsum, s);
            }
        }

        many = many || mall;
        if (!mall) {                 // ncc unused when any tap masked
            vscore[n] = THR;
            continue;
        }
        float dmean = __fdiv_rn(dsum, 25.f);
        float dvar = 0.f, cross = 0.f;
#pragma unroll
        for (int p = 0; p < PS; p++) {
            float dc = __fsub_rn(samp[p], dmean);
            dvar  = __fadd_rn(dvar,  __fmul_rn(dc, dc));
            cross = __fadd_rn(cross, __fmul_rn(sc[p], dc));
        }
        dvar  = __fdiv_rn(dvar, 25.f);
        cross = __fdiv_rn(cross, 25.f);
        float prod = __fmul_rn(svar, dvar);
        vscore[n] = (prod > 0.f) ? __fdiv_rn(cross, __fsqrt_rn(prod)) : THR;
    }

    float ssc = __fadd_rn(__fadd_rn(__fadd_rn(vscore[0], vscore[1]), vscore[2]),
                          vscore[3]);
    float score = many ? __fdiv_rn(ssc, 4.f) : THR;
    g_score[idx] = score;
    g_many[idx]  = many ? (unsigned char)1 : (unsigned char)0;
}

// ---------------------------------------------------------------------------
__global__ void __launch_bounds__(128)
ncc_final_kernel(const float* __restrict__ depth,
                 const float* __restrict__ norm,
                 float* __restrict__ out) {
    using namespace cfg;
    int pix = blockIdx.x * blockDim.x + threadIdx.x;
    if (pix >= HW) return;

    float best = g_score[pix];
    int bd = 0;
#pragma unroll
    for (int dd = 1; dd < DS; dd++) {
        float s = g_score[dd * HW + pix];
        if (s > best) { best = s; bd = dd; }   // strict >: first-max semantics
    }

    int h = pix / W;
    int w = pix - h * W;
    int pd = perm_d(bd);
    int pi = pd / 3 - 1;
    int pj = pd % 3 - 1;

    int hd = h + DIL * pi, wd = w + DIL * pj;
    float dp = 0.f;
    if (hd >= 0 && hd < H && wd >= 0 && wd < W) dp = depth[hd * W + wd];

    int hn = h + pi, wn = w + pj;
    float nx = 0.f, ny = 0.f, nz = 0.f;
    if (hn >= 0 && hn < H && wn >= 0 && wn < W) {
        int o = hn * W + wn;
        nx = norm[o];
        ny = norm[HW + o];
        nz = norm[2 * HW + o];
    }

    out[pix]          = __fsub_rn(1.f, best);
    out[HW + pix]     = dp;
    out[2 * HW + pix] = nx;
    out[3 * HW + pix] = ny;
    out[4 * HW + pix] = nz;
    out[5 * HW + pix] = g_many[bd * HW + pix] ? 1.f : 0.f;
}

// ---------------------------------------------------------------------------
extern "C" void kernel_launch(void* const* d_in, const int* in_sizes, int n_in,
                              void* d_out, int out_size) {
    const float* src   = (const float*)d_in[0];
    const float* dst   = (const float*)d_in[1];
    const float* Ks    = (const float*)d_in[2];
    const float* Rs    = (const float*)d_in[3];
    const float* Ts    = (const float*)d_in[4];
    const float* depth = (const float*)d_in[5];
    const float* norm  = (const float*)d_in[6];
    float* out = (float*)d_out;

    precompute_kernel<<<1, 32>>>(Ks, Rs, Ts);
    int total = cfg::DS * cfg::HW;
    ncc_score_kernel<<<(total + 127) / 128, 128>>>(src, dst, depth, norm);
    ncc_final_kernel<<<(cfg::HW + 127) / 128, 128>>>(depth, norm, out);
}

// round 11
// speedup vs baseline: 1.7450x; 1.7450x over previous
#include <cuda_runtime.h>

// ---------------------------------------------------------------------------
// NCC plane-sweep forward (B=1, N=4, H=160, W=192, patch 5x5, 9 depth taps,
// depth dilation 2). Arithmetic FROZEN from R9 (bit-exact vs reference):
//   PP=K·R: FMA-ascending; Hmat chain: mul+add; tap matvec: FMA-ascending;
//   all divides IEEE div.rn; score reductions mul+add.
// R10: scheduling/storage only —
//   - src patch via shared-memory row tile (drops sp[25]/sc[25] regs)
//   - gather indices packed u16, re-gather in pass 2 (drops samp[25] regs)
//   - border/invalid early-out (score=THR, no divides)
//   - per-view early break on first masked tap
// ---------------------------------------------------------------------------

namespace cfg {
constexpr int H = 160;
constexpr int W = 192;
constexpr int NVIEW = 4;
constexpr int DS = 9;
constexpr int DIL = 2;
constexpr int PS = 25;
constexpr int HW = H * W;
constexpr float THR = 0.5f;
constexpr int TILE_C = W + 4;   // 196
}

__device__ float g_PP[cfg::NVIEW][9];    // K * R
__device__ float g_K0[cfg::NVIEW][9];    // K^-1 (Ks[:, :, 0])
__device__ float g_T[cfg::NVIEW][3];
__device__ float g_score[cfg::DS * cfg::HW];
__device__ unsigned char g_many[cfg::DS * cfg::HW];

__device__ __forceinline__ int perm_d(int d) {
    return (d == 0) ? 4 : (d == 4) ? 0 : d;
}

// Plain mul+add sequential chain (no FMA)
__device__ __forceinline__ float dot3m(float a0, float b0, float a1, float b1,
                                       float a2, float b2) {
    return __fadd_rn(__fadd_rn(__fmul_rn(a0, b0), __fmul_rn(a1, b1)),
                     __fmul_rn(a2, b2));
}

// Ascending FMA chain, zero init
__device__ __forceinline__ float dot3f(float a0, float b0, float a1, float b1,
                                       float a2, float b2) {
    return fmaf(a2, b2, fmaf(a1, b1, __fmul_rn(a0, b0)));
}

// ---------------------------------------------------------------------------
__global__ void precompute_kernel(const float* __restrict__ Ks,
                                  const float* __restrict__ Rs,
                                  const float* __restrict__ Ts) {
    int n = threadIdx.x;
    if (n >= cfg::NVIEW) return;
    const float* Ki = Ks + n * 18;       // Ks[0,n,0] = K^-1
    const float* K  = Ks + n * 18 + 9;   // Ks[0,n,1] = K
    const float* R  = Rs + n * 9;
#pragma unroll
    for (int i = 0; i < 3; i++)
#pragma unroll
        for (int j = 0; j < 3; j++)
            g_PP[n][i * 3 + j] = dot3f(K[i * 3 + 0], R[0 * 3 + j],
                                       K[i * 3 + 1], R[1 * 3 + j],
                                       K[i * 3 + 2], R[2 * 3 + j]);
#pragma unroll
    for (int i = 0; i < 9; i++) g_K0[n][i] = Ki[i];
#pragma unroll
    for (int i = 0; i < 3; i++) g_T[n][i] = Ts[n * 3 + i];
}

// ---------------------------------------------------------------------------
// Block = one (image row h, depth tap d). 192 threads = one pixel each.
__global__ void __launch_bounds__(192)
ncc_score_kernel(const float* __restrict__ src,
                 const float* __restrict__ dst,
                 const float* __restrict__ depth,
                 const float* __restrict__ norm) {
    using namespace cfg;
    __shared__ float tile[5][TILE_C];

    const int h = blockIdx.x;
    const int d = blockIdx.y;
    const int w = threadIdx.x;

    // cooperative src tile load: rows h-2..h+2, cols -2..W+1 (zero-padded)
    for (int t = threadIdx.x; t < 5 * TILE_C; t += 192) {
        int r = t / TILE_C;
        int c = t - r * TILE_C - 2;
        int gr = h - 2 + r;
        float v = 0.f;
        if (gr >= 0 && gr < H && c >= 0 && c < W) v = src[gr * W + c];
        tile[r][t - r * TILE_C] = v;
    }
    __syncthreads();

    const int idx = d * HW + h * W + w;
    const int pd = perm_d(d);
    const int pi = pd / 3 - 1;
    const int pj = pd % 3 - 1;

    // dilated depth tap (zero-padded)
    int hd = h + DIL * pi, wd = w + DIL * pj;
    float dp = 0.f;
    if (hd >= 0 && hd < H && wd >= 0 && wd < W) dp = depth[hd * W + wd];

    // normal tap (dilation 1, zero-padded)
    int hn = h + pi, wn = w + pj;
    float nv0 = 0.f, nv1 = 0.f, nv2 = 0.f;
    if (hn >= 0 && hn < H && wn >= 0 && wn < W) {
        int o = hn * W + wn;
        nv0 = norm[o];
        nv1 = norm[HW + o];
        nv2 = norm[2 * HW + o];
    }
    bool valid_dn = (dp > 0.f) && (nv2 < 0.f);

    // Early-out: any src-patch tap OOB, or invalid depth/normal, forces
    // mall=false for every view -> many=false -> score=THR exactly.
    bool interior = (h >= 2) && (h < H - 2) && (w >= 2) && (w < W - 2);
    if (!interior || !valid_dn) {
        g_score[idx] = THR;
        g_many[idx]  = 0;
        return;
    }

    float dsafe = dp;   // dp > 0 here, so dsafe == dp (reference: dp!=0 ? dp : 1)

    // src patch stats from tile (identical op order to reference)
    float ssum = 0.f;
#pragma unroll
    for (int p = 0; p < PS; p++)
        ssum = __fadd_rn(ssum, tile[p / 5][w + (p % 5)]);
    float smean = __fdiv_rn(ssum, 25.f);
    float svar = 0.f;
#pragma unroll
    for (int p = 0; p < PS; p++) {
        float scv = __fsub_rn(tile[p / 5][w + (p % 5)], smean);
        svar = __fadd_rn(svar, __fmul_rn(scv, scv));
    }
    svar = __fdiv_rn(svar, 25.f);

    const float fw = (float)w, fh = (float)h;
    float vscore[NVIEW];
    bool many = false;

#pragma unroll
    for (int n = 0; n < NVIEW; n++) {
        // m = I - (T_i * n_j) / dsafe  (entry-wise IEEE ops)
        float mM[9];
#pragma unroll
        for (int i = 0; i < 3; i++) {
            float Ti = g_T[n][i];
            float q0 = __fdiv_rn(__fmul_rn(Ti, nv0), dsafe);
            float q1 = __fdiv_rn(__fmul_rn(Ti, nv1), dsafe);
            float q2 = __fdiv_rn(__fmul_rn(Ti, nv2), dsafe);
            mM[i * 3 + 0] = __fsub_rn((i == 0) ? 1.f : 0.f, q0);
            mM[i * 3 + 1] = __fsub_rn((i == 1) ? 1.f : 0.f, q1);
            mM[i * 3 + 2] = __fsub_rn((i == 2) ? 1.f : 0.f, q2);
        }
        // tmp = PP @ m ; Hm = tmp @ K0  (mul+add chains)
        float tmp[9], Hm[9];
#pragma unroll
        for (int i = 0; i < 3; i++)
#pragma unroll
            for (int k = 0; k < 3; k++)
                tmp[i * 3 + k] = dot3m(g_PP[n][i * 3 + 0], mM[0 * 3 + k],
                                       g_PP[n][i * 3 + 1], mM[1 * 3 + k],
                                       g_PP[n][i * 3 + 2], mM[2 * 3 + k]);
#pragma unroll
        for (int i = 0; i < 3; i++)
#pragma unroll
            for (int l = 0; l < 3; l++)
                Hm[i * 3 + l] = dot3m(tmp[i * 3 + 0], g_K0[n][0 * 3 + l],
                                      tmp[i * 3 + 1], g_K0[n][1 * 3 + l],
                                      tmp[i * 3 + 2], g_K0[n][2 * 3 + l]);

        const float* dstn = dst + n * HW;
        unsigned idxp[13];          // 25 gather indices packed as u16 pairs
        bool mall = true;
        float dsum = 0.f;

#pragma unroll
        for (int p = 0; p < PS; p++) {
            float cy = fh + (float)(p / 5 - 2);
            float cx = fw + (float)(p % 5 - 2);
            float X0 = dot3f(Hm[0], cx, Hm[1], cy, Hm[2], 1.f);
            float X1 = dot3f(Hm[3], cx, Hm[4], cy, Hm[5], 1.f);
            float z  = dot3f(Hm[6], cx, Hm[7], cy, Hm[8], 1.f);
            float zs = (z != 0.f) ? z : 1.f;
            float xw = __fdiv_rn(X0, zs);
            float yw = __fdiv_rn(X1, zs);
            bool ok = (z > 0.f) &&
                      (xw > 0.f) && (xw < (float)(W - 1)) &&
                      (yw > 0.f) && (yw < (float)(H - 1));
            if (!ok) { mall = false; break; }   // rest of view unused
            unsigned lin = (unsigned)((int)yw * W + (int)xw);
            if ((p & 1) == 0) idxp[p >> 1] = lin;
            else              idxp[p >> 1] |= lin << 16;
            dsum = __fadd_rn(dsum, dstn[lin]);
        }

        many = many || mall;
        if (!mall) { vscore[n] = THR; continue; }

        // pass 2: re-gather by stored indices (identical values), exact NCC
        float dmean = __fdiv_rn(dsum, 25.f);
        float dvar = 0.f, cross = 0.f;
#pragma unroll
        for (int p = 0; p < PS; p++) {
            unsigned lin = (idxp[p >> 1] >> ((p & 1) * 16)) & 0xFFFFu;
            float s  = dstn[lin];
            float dc = __fsub_rn(s, dmean);
            dvar  = __fadd_rn(dvar,  __fmul_rn(dc, dc));
            float scv = __fsub_rn(tile[p / 5][w + (p % 5)], smean);
            cross = __fadd_rn(cross, __fmul_rn(scv, dc));
        }
        dvar  = __fdiv_rn(dvar, 25.f);
        cross = __fdiv_rn(cross, 25.f);
        float prod = __fmul_rn(svar, dvar);
        vscore[n] = (prod > 0.f) ? __fdiv_rn(cross, __fsqrt_rn(prod)) : THR;
    }

    float ssc = __fadd_rn(__fadd_rn(__fadd_rn(vscore[0], vscore[1]), vscore[2]),
                          vscore[3]);
    g_score[idx] = many ? __fdiv_rn(ssc, 4.f) : THR;
    g_many[idx]  = many ? (unsigned char)1 : (unsigned char)0;
}

// ---------------------------------------------------------------------------
__global__ void __launch_bounds__(128)
ncc_final_kernel(const float* __restrict__ depth,
                 const float* __restrict__ norm,
                 float* __restrict__ out) {
    using namespace cfg;
    int pix = blockIdx.x * blockDim.x + threadIdx.x;
    if (pix >= HW) return;

    float best = g_score[pix];
    int bd = 0;
#pragma unroll
    for (int dd = 1; dd < DS; dd++) {
        float s = g_score[dd * HW + pix];
        if (s > best) { best = s; bd = dd; }   // strict >: first-max semantics
    }

    int h = pix / W;
    int w = pix - h * W;
    int pd = perm_d(bd);
    int pi = pd / 3 - 1;
    int pj = pd % 3 - 1;

    int hd = h + DIL * pi, wd = w + DIL * pj;
    float dp = 0.f;
    if (hd >= 0 && hd < H && wd >= 0 && wd < W) dp = depth[hd * W + wd];

    int hn = h + pi, wn = w + pj;
    float nx = 0.f, ny = 0.f, nz = 0.f;
    if (hn >= 0 && hn < H && wn >= 0 && wn < W) {
        int o = hn * W + wn;
        nx = norm[o];
        ny = norm[HW + o];
        nz = norm[2 * HW + o];
    }

    out[pix]          = __fsub_rn(1.f, best);
    out[HW + pix]     = dp;
    out[2 * HW + pix] = nx;
    out[3 * HW + pix] = ny;
    out[4 * HW + pix] = nz;
    out[5 * HW + pix] = g_many[bd * HW + pix] ? 1.f : 0.f;
}

// ---------------------------------------------------------------------------
extern "C" void kernel_launch(void* const* d_in, const int* in_sizes, int n_in,
                              void* d_out, int out_size) {
    const float* src   = (const float*)d_in[0];
    const float* dst   = (const float*)d_in[1];
    const float* Ks    = (const float*)d_in[2];
    const float* Rs    = (const float*)d_in[3];
    const float* Ts    = (const float*)d_in[4];
    const float* depth = (const float*)d_in[5];
    const float* norm  = (const float*)d_in[6];
    float* out = (float*)d_out;

    precompute_kernel<<<1, 32>>>(Ks, Rs, Ts);
    dim3 grid(cfg::H, cfg::DS);
    ncc_score_kernel<<<grid, 192>>>(src, dst, depth, norm);
    ncc_final_kernel<<<(cfg::HW + 127) / 128, 128>>>(depth, norm, out);
}

// round 12
// speedup vs baseline: 2.1374x; 1.2248x over previous
#include <cuda_runtime.h>

// ---------------------------------------------------------------------------
// NCC plane-sweep forward (B=1, N=4, H=160, W=192, patch 5x5, 9 depth taps,
// depth dilation 2). Arithmetic FROZEN (bit-exact vs reference since R9):
//   PP=K·R: FMA-ascending; Hmat chain: mul+add; tap matvec: FMA-ascending;
//   all divides IEEE div.rn; score reductions mul+add; view sum sequential.
// R11: view-level parallelism — gridDim.z = NVIEW, one view per thread.
//   Per-view score/mask staged in device globals; final kernel does the
//   sequential 4-view sum (identical op order) + argmax + output assembly.
//   samp[] back in registers (single gather pass).
// ---------------------------------------------------------------------------

namespace cfg {
constexpr int H = 160;
constexpr int W = 192;
constexpr int NVIEW = 4;
constexpr int DS = 9;
constexpr int DIL = 2;
constexpr int PS = 25;
constexpr int HW = H * W;
constexpr float THR = 0.5f;
constexpr int TILE_C = W + 4;   // 196
}

__device__ float g_PP[cfg::NVIEW][9];    // K * R
__device__ float g_K0[cfg::NVIEW][9];    // K^-1 (Ks[:, :, 0])
__device__ float g_T[cfg::NVIEW][3];
// per-(depth-tap, view, pixel) staging: [DS][NVIEW][HW]
__device__ float g_vs[cfg::DS * cfg::NVIEW * cfg::HW];
__device__ unsigned char g_mb[cfg::DS * cfg::NVIEW * cfg::HW];

__device__ __forceinline__ int perm_d(int d) {
    return (d == 0) ? 4 : (d == 4) ? 0 : d;
}

// Plain mul+add sequential chain (no FMA)
__device__ __forceinline__ float dot3m(float a0, float b0, float a1, float b1,
                                       float a2, float b2) {
    return __fadd_rn(__fadd_rn(__fmul_rn(a0, b0), __fmul_rn(a1, b1)),
                     __fmul_rn(a2, b2));
}

// Ascending FMA chain, zero init
__device__ __forceinline__ float dot3f(float a0, float b0, float a1, float b1,
                                       float a2, float b2) {
    return fmaf(a2, b2, fmaf(a1, b1, __fmul_rn(a0, b0)));
}

// ---------------------------------------------------------------------------
__global__ void precompute_kernel(const float* __restrict__ Ks,
                                  const float* __restrict__ Rs,
                                  const float* __restrict__ Ts) {
    int n = threadIdx.x;
    if (n >= cfg::NVIEW) return;
    const float* Ki = Ks + n * 18;       // Ks[0,n,0] = K^-1
    const float* K  = Ks + n * 18 + 9;   // Ks[0,n,1] = K
    const float* R  = Rs + n * 9;
#pragma unroll
    for (int i = 0; i < 3; i++)
#pragma unroll
        for (int j = 0; j < 3; j++)
            g_PP[n][i * 3 + j] = dot3f(K[i * 3 + 0], R[0 * 3 + j],
                                       K[i * 3 + 1], R[1 * 3 + j],
                                       K[i * 3 + 2], R[2 * 3 + j]);
#pragma unroll
    for (int i = 0; i < 9; i++) g_K0[n][i] = Ki[i];
#pragma unroll
    for (int i = 0; i < 3; i++) g_T[n][i] = Ts[n * 3 + i];
}

// ---------------------------------------------------------------------------
// Block = (image row h, depth tap d, view n). 192 threads = one pixel each.
__global__ void __launch_bounds__(192)
ncc_view_kernel(const float* __restrict__ src,
                const float* __restrict__ dst,
                const float* __restrict__ depth,
                const float* __restrict__ norm) {
    using namespace cfg;
    __shared__ float tile[5][TILE_C];

    const int h = blockIdx.x;
    const int d = blockIdx.y;
    const int n = blockIdx.z;
    const int w = threadIdx.x;

    // cooperative src tile load: rows h-2..h+2, cols -2..W+1 (zero-padded)
    for (int t = threadIdx.x; t < 5 * TILE_C; t += 192) {
        int r = t / TILE_C;
        int c = t - r * TILE_C - 2;
        int gr = h - 2 + r;
        float v = 0.f;
        if (gr >= 0 && gr < H && c >= 0 && c < W) v = src[gr * W + c];
        tile[r][t - r * TILE_C] = v;
    }
    __syncthreads();

    const int sidx = (d * NVIEW + n) * HW + h * W + w;
    const int pd = perm_d(d);
    const int pi = pd / 3 - 1;
    const int pj = pd % 3 - 1;

    // dilated depth tap (zero-padded)
    int hd = h + DIL * pi, wd = w + DIL * pj;
    float dp = 0.f;
    if (hd >= 0 && hd < H && wd >= 0 && wd < W) dp = depth[hd * W + wd];

    // normal tap (dilation 1, zero-padded)
    int hn = h + pi, wn = w + pj;
    float nv0 = 0.f, nv1 = 0.f, nv2 = 0.f;
    if (hn >= 0 && hn < H && wn >= 0 && wn < W) {
        int o = hn * W + wn;
        nv0 = norm[o];
        nv1 = norm[HW + o];
        nv2 = norm[2 * HW + o];
    }
    bool valid_dn = (dp > 0.f) && (nv2 < 0.f);
    bool interior = (h >= 2) && (h < H - 2) && (w >= 2) && (w < W - 2);

    if (!interior || !valid_dn) {      // mall=false exactly (src tap OOB/invalid)
        g_vs[sidx] = THR;
        g_mb[sidx] = 0;
        return;
    }

    const float dsafe = dp;  // dp > 0 here

    // m = I - (T_i * n_j) / dsafe  (entry-wise IEEE ops)
    float mM[9];
#pragma unroll
    for (int i = 0; i < 3; i++) {
        float Ti = g_T[n][i];
        float q0 = __fdiv_rn(__fmul_rn(Ti, nv0), dsafe);
        float q1 = __fdiv_rn(__fmul_rn(Ti, nv1), dsafe);
        float q2 = __fdiv_rn(__fmul_rn(Ti, nv2), dsafe);
        mM[i * 3 + 0] = __fsub_rn((i == 0) ? 1.f : 0.f, q0);
        mM[i * 3 + 1] = __fsub_rn((i == 1) ? 1.f : 0.f, q1);
        mM[i * 3 + 2] = __fsub_rn((i == 2) ? 1.f : 0.f, q2);
    }
    // tmp = PP @ m ; Hm = tmp @ K0  (mul+add chains)
    float tmp[9], Hm[9];
#pragma unroll
    for (int i = 0; i < 3; i++)
#pragma unroll
        for (int k = 0; k < 3; k++)
            tmp[i * 3 + k] = dot3m(g_PP[n][i * 3 + 0], mM[0 * 3 + k],
                                   g_PP[n][i * 3 + 1], mM[1 * 3 + k],
                                   g_PP[n][i * 3 + 2], mM[2 * 3 + k]);
#pragma unroll
    for (int i = 0; i < 3; i++)
#pragma unroll
        for (int l = 0; l < 3; l++)
            Hm[i * 3 + l] = dot3m(tmp[i * 3 + 0], g_K0[n][0 * 3 + l],
                                  tmp[i * 3 + 1], g_K0[n][1 * 3 + l],
                                  tmp[i * 3 + 2], g_K0[n][2 * 3 + l]);

    const float* dstn = dst + n * HW;
    const float fw = (float)w, fh = (float)h;
    float samp[PS];
    bool mall = true;
    float dsum = 0.f;

#pragma unroll
    for (int p = 0; p < PS; p++) {
        float cy = fh + (float)(p / 5 - 2);
        float cx = fw + (float)(p % 5 - 2);
        float X0 = dot3f(Hm[0], cx, Hm[1], cy, Hm[2], 1.f);
        float X1 = dot3f(Hm[3], cx, Hm[4], cy, Hm[5], 1.f);
        float z  = dot3f(Hm[6], cx, Hm[7], cy, Hm[8], 1.f);
        float zs = (z != 0.f) ? z : 1.f;
        float xw = __fdiv_rn(X0, zs);
        float yw = __fdiv_rn(X1, zs);
        bool ok = (z > 0.f) &&
                  (xw > 0.f) && (xw < (float)(W - 1)) &&
                  (yw > 0.f) && (yw < (float)(H - 1));
        if (!ok) { mall = false; break; }   // rest of this view unused
        float s = dstn[(int)yw * W + (int)xw];
        samp[p] = s;
        dsum = __fadd_rn(dsum, s);
    }

    if (!mall) {
        g_vs[sidx] = THR;
        g_mb[sidx] = 0;
        return;
    }

    // src patch stats (identical op order to reference)
    float ssum = 0.f;
#pragma unroll
    for (int p = 0; p < PS; p++)
        ssum = __fadd_rn(ssum, tile[p / 5][w + (p % 5)]);
    float smean = __fdiv_rn(ssum, 25.f);
    float svar = 0.f;
#pragma unroll
    for (int p = 0; p < PS; p++) {
        float scv = __fsub_rn(tile[p / 5][w + (p % 5)], smean);
        svar = __fadd_rn(svar, __fmul_rn(scv, scv));
    }
    svar = __fdiv_rn(svar, 25.f);

    float dmean = __fdiv_rn(dsum, 25.f);
    float dvar = 0.f, cross = 0.f;
#pragma unroll
    for (int p = 0; p < PS; p++) {
        float dc = __fsub_rn(samp[p], dmean);
        dvar  = __fadd_rn(dvar,  __fmul_rn(dc, dc));
        float scv = __fsub_rn(tile[p / 5][w + (p % 5)], smean);
        cross = __fadd_rn(cross, __fmul_rn(scv, dc));
    }
    dvar  = __fdiv_rn(dvar, 25.f);
    cross = __fdiv_rn(cross, 25.f);
    float prod = __fmul_rn(svar, dvar);
    g_vs[sidx] = (prod > 0.f) ? __fdiv_rn(cross, __fsqrt_rn(prod)) : THR;
    g_mb[sidx] = 1;
}

// ---------------------------------------------------------------------------
// Final: per-pixel view combine (sequential sum, identical order), argmax
// over 9 depth taps (strict >, first-max), output assembly.
__global__ void __launch_bounds__(128)
ncc_final_kernel(const float* __restrict__ depth,
                 const float* __restrict__ norm,
                 float* __restrict__ out) {
    using namespace cfg;
    int pix = blockIdx.x * blockDim.x + threadIdx.x;
    if (pix >= HW) return;

    float best = -1e30f;
    int bd = 0;
    bool bmany = false;
#pragma unroll
    for (int dd = 0; dd < DS; dd++) {
        const int base = dd * NVIEW * HW + pix;
        float v0 = g_vs[base];
        float v1 = g_vs[base + HW];
        float v2 = g_vs[base + 2 * HW];
        float v3 = g_vs[base + 3 * HW];
        bool many = (g_mb[base] | g_mb[base + HW] |
                     g_mb[base + 2 * HW] | g_mb[base + 3 * HW]) != 0;
        float ssc = __fadd_rn(__fadd_rn(__fadd_rn(v0, v1), v2), v3);
        float score = many ? __fdiv_rn(ssc, 4.f) : THR;
        if (score > best) { best = score; bd = dd; bmany = many; }
    }

    int h = pix / W;
    int w = pix - h * W;
    int pd = perm_d(bd);
    int pi = pd / 3 - 1;
    int pj = pd % 3 - 1;

    int hd = h + DIL * pi, wd = w + DIL * pj;
    float dp = 0.f;
    if (hd >= 0 && hd < H && wd >= 0 && wd < W) dp = depth[hd * W + wd];

    int hn = h + pi, wn = w + pj;
    float nx = 0.f, ny = 0.f, nz = 0.f;
    if (hn >= 0 && hn < H && wn >= 0 && wn < W) {
        int o = hn * W + wn;
        nx = norm[o];
        ny = norm[HW + o];
        nz = norm[2 * HW + o];
    }

    out[pix]          = __fsub_rn(1.f, best);
    out[HW + pix]     = dp;
    out[2 * HW + pix] = nx;
    out[3 * HW + pix] = ny;
    out[4 * HW + pix] = nz;
    out[5 * HW + pix] = bmany ? 1.f : 0.f;
}

// ---------------------------------------------------------------------------
extern "C" void kernel_launch(void* const* d_in, const int* in_sizes, int n_in,
                              void* d_out, int out_size) {
    const float* src   = (const float*)d_in[0];
    const float* dst   = (const float*)d_in[1];
    const float* Ks    = (const float*)d_in[2];
    const float* Rs    = (const float*)d_in[3];
    const float* Ts    = (const float*)d_in[4];
    const float* depth = (const float*)d_in[5];
    const float* norm  = (const float*)d_in[6];
    float* out = (float*)d_out;

    precompute_kernel<<<1, 32>>>(Ks, Rs, Ts);
    dim3 grid(cfg::H, cfg::DS, cfg::NVIEW);
    ncc_view_kernel<<<grid, 192>>>(src, dst, depth, norm);
    ncc_final_kernel<<<(cfg::HW + 127) / 128, 128>>>(depth, norm, out);
}

// round 13
// speedup vs baseline: 2.5116x; 1.1751x over previous
#include <cuda_runtime.h>

// ---------------------------------------------------------------------------
// NCC plane-sweep forward (B=1, N=4, H=160, W=192, patch 5x5, 9 depth taps,
// depth dilation 2). Arithmetic FROZEN (bit-exact vs reference since R9):
//   PP=K·R: FMA-ascending; Hmat chain: mul+add; tap matvec: FMA-ascending;
//   all divides IEEE div.rn; reductions mul+add; view sum sequential.
// R12 (scheduling only): MIO-op reduction —
//   - per-pixel src stats hoisted to a stats kernel (smean/svar reused 36x)
//   - shared tile removed: interior-only cross loop reads src directly (L1)
//   - flat 256-thread blocks, no __syncthreads
// ---------------------------------------------------------------------------

namespace cfg {
constexpr int H = 160;
constexpr int W = 192;
constexpr int NVIEW = 4;
constexpr int DS = 9;
constexpr int DIL = 2;
constexpr int PS = 25;
constexpr int HW = H * W;
constexpr float THR = 0.5f;
}

__device__ float g_PP[cfg::NVIEW][9];    // K * R
__device__ float g_K0[cfg::NVIEW][9];    // K^-1 (Ks[:, :, 0])
__device__ float g_T[cfg::NVIEW][3];
__device__ float g_smean[cfg::HW];
__device__ float g_svar[cfg::HW];
// per-(depth-tap, view, pixel) staging: [DS][NVIEW][HW]
__device__ float g_vs[cfg::DS * cfg::NVIEW * cfg::HW];
__device__ unsigned char g_mb[cfg::DS * cfg::NVIEW * cfg::HW];

__device__ __forceinline__ int perm_d(int d) {
    return (d == 0) ? 4 : (d == 4) ? 0 : d;
}

// Plain mul+add sequential chain (no FMA)
__device__ __forceinline__ float dot3m(float a0, float b0, float a1, float b1,
                                       float a2, float b2) {
    return __fadd_rn(__fadd_rn(__fmul_rn(a0, b0), __fmul_rn(a1, b1)),
                     __fmul_rn(a2, b2));
}

// Ascending FMA chain, zero init
__device__ __forceinline__ float dot3f(float a0, float b0, float a1, float b1,
                                       float a2, float b2) {
    return fmaf(a2, b2, fmaf(a1, b1, __fmul_rn(a0, b0)));
}

// ---------------------------------------------------------------------------
__global__ void precompute_kernel(const float* __restrict__ Ks,
                                  const float* __restrict__ Rs,
                                  const float* __restrict__ Ts) {
    int n = threadIdx.x;
    if (n >= cfg::NVIEW) return;
    const float* Ki = Ks + n * 18;       // Ks[0,n,0] = K^-1
    const float* K  = Ks + n * 18 + 9;   // Ks[0,n,1] = K
    const float* R  = Rs + n * 9;
#pragma unroll
    for (int i = 0; i < 3; i++)
#pragma unroll
        for (int j = 0; j < 3; j++)
            g_PP[n][i * 3 + j] = dot3f(K[i * 3 + 0], R[0 * 3 + j],
                                       K[i * 3 + 1], R[1 * 3 + j],
                                       K[i * 3 + 2], R[2 * 3 + j]);
#pragma unroll
    for (int i = 0; i < 9; i++) g_K0[n][i] = Ki[i];
#pragma unroll
    for (int i = 0; i < 3; i++) g_T[n][i] = Ts[n * 3 + i];
}

// ---------------------------------------------------------------------------
// Per-pixel src patch stats (identical op order to reference), computed once.
__global__ void __launch_bounds__(256)
stats_kernel(const float* __restrict__ src) {
    using namespace cfg;
    int pix = blockIdx.x * blockDim.x + threadIdx.x;
    if (pix >= HW) return;
    int h = pix / W;
    int w = pix - h * W;

    float sp[PS];
    float ssum = 0.f;
#pragma unroll
    for (int p = 0; p < PS; p++) {
        int hh = h + p / 5 - 2, ww = w + p % 5 - 2;
        float v = 0.f;
        if (hh >= 0 && hh < H && ww >= 0 && ww < W) v = src[hh * W + ww];
        sp[p] = v;
        ssum = __fadd_rn(ssum, v);
    }
    float smean = __fdiv_rn(ssum, 25.f);
    float svar = 0.f;
#pragma unroll
    for (int p = 0; p < PS; p++) {
        float scv = __fsub_rn(sp[p], smean);
        svar = __fadd_rn(svar, __fmul_rn(scv, scv));
    }
    g_smean[pix] = smean;
    g_svar[pix]  = __fdiv_rn(svar, 25.f);
}

// ---------------------------------------------------------------------------
// Flat: one thread per (pixel, depth tap d [grid.y], view n [grid.z]).
__global__ void __launch_bounds__(256)
ncc_view_kernel(const float* __restrict__ src,
                const float* __restrict__ dst,
                const float* __restrict__ depth,
                const float* __restrict__ norm) {
    using namespace cfg;
    const int pix = blockIdx.x * blockDim.x + threadIdx.x;
    if (pix >= HW) return;
    const int d = blockIdx.y;
    const int n = blockIdx.z;
    const int h = pix / W;
    const int w = pix - h * W;

    const int sidx = (d * NVIEW + n) * HW + pix;
    const int pd = perm_d(d);
    const int pi = pd / 3 - 1;
    const int pj = pd % 3 - 1;

    // dilated depth tap (zero-padded)
    int hd = h + DIL * pi, wd = w + DIL * pj;
    float dp = 0.f;
    if (hd >= 0 && hd < H && wd >= 0 && wd < W) dp = depth[hd * W + wd];

    // normal tap (dilation 1, zero-padded)
    int hn = h + pi, wn = w + pj;
    float nv0 = 0.f, nv1 = 0.f, nv2 = 0.f;
    if (hn >= 0 && hn < H && wn >= 0 && wn < W) {
        int o = hn * W + wn;
        nv0 = norm[o];
        nv1 = norm[HW + o];
        nv2 = norm[2 * HW + o];
    }
    bool valid_dn = (dp > 0.f) && (nv2 < 0.f);
    bool interior = (h >= 2) && (h < H - 2) && (w >= 2) && (w < W - 2);

    if (!interior || !valid_dn) {   // any src tap OOB / invalid -> mall=false
        g_vs[sidx] = THR;
        g_mb[sidx] = 0;
        return;
    }

    const float dsafe = dp;  // dp > 0 here

    // m = I - (T_i * n_j) / dsafe  (entry-wise IEEE ops)
    float mM[9];
#pragma unroll
    for (int i = 0; i < 3; i++) {
        float Ti = g_T[n][i];
        float q0 = __fdiv_rn(__fmul_rn(Ti, nv0), dsafe);
        float q1 = __fdiv_rn(__fmul_rn(Ti, nv1), dsafe);
        float q2 = __fdiv_rn(__fmul_rn(Ti, nv2), dsafe);
        mM[i * 3 + 0] = __fsub_rn((i == 0) ? 1.f : 0.f, q0);
        mM[i * 3 + 1] = __fsub_rn((i == 1) ? 1.f : 0.f, q1);
        mM[i * 3 + 2] = __fsub_rn((i == 2) ? 1.f : 0.f, q2);
    }
    // tmp = PP @ m ; Hm = tmp @ K0  (mul+add chains)
    float tmp[9], Hm[9];
#pragma unroll
    for (int i = 0; i < 3; i++)
#pragma unroll
        for (int k = 0; k < 3; k++)
            tmp[i * 3 + k] = dot3m(g_PP[n][i * 3 + 0], mM[0 * 3 + k],
                                   g_PP[n][i * 3 + 1], mM[1 * 3 + k],
                                   g_PP[n][i * 3 + 2], mM[2 * 3 + k]);
#pragma unroll
    for (int i = 0; i < 3; i++)
#pragma unroll
        for (int l = 0; l < 3; l++)
            Hm[i * 3 + l] = dot3m(tmp[i * 3 + 0], g_K0[n][0 * 3 + l],
                                  tmp[i * 3 + 1], g_K0[n][1 * 3 + l],
                                  tmp[i * 3 + 2], g_K0[n][2 * 3 + l]);

    const float* dstn = dst + n * HW;
    const float fw = (float)w, fh = (float)h;
    float samp[PS];
    bool mall = true;
    float dsum = 0.f;

#pragma unroll
    for (int p = 0; p < PS; p++) {
        float cy = fh + (float)(p / 5 - 2);
        float cx = fw + (float)(p % 5 - 2);
        float X0 = dot3f(Hm[0], cx, Hm[1], cy, Hm[2], 1.f);
        float X1 = dot3f(Hm[3], cx, Hm[4], cy, Hm[5], 1.f);
        float z  = dot3f(Hm[6], cx, Hm[7], cy, Hm[8], 1.f);
        float zs = (z != 0.f) ? z : 1.f;
        float xw = __fdiv_rn(X0, zs);
        float yw = __fdiv_rn(X1, zs);
        bool ok = (z > 0.f) &&
                  (xw > 0.f) && (xw < (float)(W - 1)) &&
                  (yw > 0.f) && (yw < (float)(H - 1));
        if (!ok) { mall = false; break; }   // rest of this view unused
        float s = dstn[(int)yw * W + (int)xw];
        samp[p] = s;
        dsum = __fadd_rn(dsum, s);
    }

    if (!mall) {
        g_vs[sidx] = THR;
        g_mb[sidx] = 0;
        return;
    }

    // NCC: stats reloaded (bit-exact), cross reads src directly (interior:
    // all 25 taps in-bounds, no padding needed)
    const float smean = g_smean[pix];
    const float svar  = g_svar[pix];
    float dmean = __fdiv_rn(dsum, 25.f);
    float dvar = 0.f, cross = 0.f;
    const float* srow = src + (h - 2) * W + (w - 2);
#pragma unroll
    for (int p = 0; p < PS; p++) {
        float dc = __fsub_rn(samp[p], dmean);
        dvar  = __fadd_rn(dvar,  __fmul_rn(dc, dc));
        float scv = __fsub_rn(srow[(p / 5) * W + (p % 5)], smean);
        cross = __fadd_rn(cross, __fmul_rn(scv, dc));
    }
    dvar  = __fdiv_rn(dvar, 25.f);
    cross = __fdiv_rn(cross, 25.f);
    float prod = __fmul_rn(svar, dvar);
    g_vs[sidx] = (prod > 0.f) ? __fdiv_rn(cross, __fsqrt_rn(prod)) : THR;
    g_mb[sidx] = 1;
}

// ---------------------------------------------------------------------------
// Final: per-pixel view combine (sequential sum, identical order), argmax
// over 9 depth taps (strict >, first-max), output assembly.
__global__ void __launch_bounds__(128)
ncc_final_kernel(const float* __restrict__ depth,
                 const float* __restrict__ norm,
                 float* __restrict__ out) {
    using namespace cfg;
    int pix = blockIdx.x * blockDim.x + threadIdx.x;
    if (pix >= HW) return;

    float best = -1e30f;
    int bd = 0;
    bool bmany = false;
#pragma unroll
    for (int dd = 0; dd < DS; dd++) {
        const int base = dd * NVIEW * HW + pix;
        float v0 = g_vs[base];
        float v1 = g_vs[base + HW];
        float v2 = g_vs[base + 2 * HW];
        float v3 = g_vs[base + 3 * HW];
        bool many = (g_mb[base] | g_mb[base + HW] |
                     g_mb[base + 2 * HW] | g_mb[base + 3 * HW]) != 0;
        float ssc = __fadd_rn(__fadd_rn(__fadd_rn(v0, v1), v2), v3);
        float score = many ? __fdiv_rn(ssc, 4.f) : THR;
        if (score > best) { best = score; bd = dd; bmany = many; }
    }

    int h = pix / W;
    int w = pix - h * W;
    int pd = perm_d(bd);
    int pi = pd / 3 - 1;
    int pj = pd % 3 - 1;

    int hd = h + DIL * pi, wd = w + DIL * pj;
    float dp = 0.f;
    if (hd >= 0 && hd < H && wd >= 0 && wd < W) dp = depth[hd * W + wd];

    int hn = h + pi, wn = w + pj;
    float nx = 0.f, ny = 0.f, nz = 0.f;
    if (hn >= 0 && hn < H && wn >= 0 && wn < W) {
        int o = hn * W + wn;
        nx = norm[o];
        ny = norm[HW + o];
        nz = norm[2 * HW + o];
    }

    out[pix]          = __fsub_rn(1.f, best);
    out[HW + pix]     = dp;
    out[2 * HW + pix] = nx;
    out[3 * HW + pix] = ny;
    out[4 * HW + pix] = nz;
    out[5 * HW + pix] = bmany ? 1.f : 0.f;
}

// ---------------------------------------------------------------------------
extern "C" void kernel_launch(void* const* d_in, const int* in_sizes, int n_in,
                              void* d_out, int out_size) {
    const float* src   = (const float*)d_in[0];
    const float* dst   = (const float*)d_in[1];
    const float* Ks    = (const float*)d_in[2];
    const float* Rs    = (const float*)d_in[3];
    const float* Ts    = (const float*)d_in[4];
    const float* depth = (const float*)d_in[5];
    const float* norm  = (const float*)d_in[6];
    float* out = (float*)d_out;

    precompute_kernel<<<1, 32>>>(Ks, Rs, Ts);
    stats_kernel<<<(cfg::HW + 255) / 256, 256>>>(src);
    dim3 grid((cfg::HW + 255) / 256, cfg::DS, cfg::NVIEW);
    ncc_view_kernel<<<grid, 256>>>(src, dst, depth, norm);
    ncc_final_kernel<<<(cfg::HW + 127) / 128, 128>>>(depth, norm, out);
}

// round 14
// speedup vs baseline: 2.5196x; 1.0032x over previous
#include <cuda_runtime.h>

// ---------------------------------------------------------------------------
// NCC plane-sweep forward (B=1, N=4, H=160, W=192, patch 5x5, 9 depth taps,
// depth dilation 2). Arithmetic FROZEN (bit-exact vs reference since R9):
//   PP=K·R: FMA-ascending; Hmat chain: mul+add; tap matvec: FMA-ascending;
//   all divides IEEE div.rn; reductions mul+add; view sum sequential.
// R13 (scheduling only):
//   - precompute merged into stats kernel (one launch fewer)
//   - staging layout [DS][HW][NVIEW]: final kernel reads float4 + u32
//     per depth tap (18 loads/thread instead of 72)
//   - z<=0 taps skip the two unused divides
// ---------------------------------------------------------------------------

namespace cfg {
constexpr int H = 160;
constexpr int W = 192;
constexpr int NVIEW = 4;
constexpr int DS = 9;
constexpr int DIL = 2;
constexpr int PS = 25;
constexpr int HW = H * W;
constexpr float THR = 0.5f;
}

__device__ float g_PP[cfg::NVIEW][9];    // K * R
__device__ float g_K0[cfg::NVIEW][9];    // K^-1 (Ks[:, :, 0])
__device__ float g_T[cfg::NVIEW][3];
__device__ float g_smean[cfg::HW];
__device__ float g_svar[cfg::HW];
// staging: scores [DS][HW] as float4 (one lane per view); masks as u32/4B
__device__ float4   g_vs4[cfg::DS * cfg::HW];
__device__ unsigned g_mb4[cfg::DS * cfg::HW];

__device__ __forceinline__ int perm_d(int d) {
    return (d == 0) ? 4 : (d == 4) ? 0 : d;
}

// Plain mul+add sequential chain (no FMA)
__device__ __forceinline__ float dot3m(float a0, float b0, float a1, float b1,
                                       float a2, float b2) {
    return __fadd_rn(__fadd_rn(__fmul_rn(a0, b0), __fmul_rn(a1, b1)),
                     __fmul_rn(a2, b2));
}

// Ascending FMA chain, zero init
__device__ __forceinline__ float dot3f(float a0, float b0, float a1, float b1,
                                       float a2, float b2) {
    return fmaf(a2, b2, fmaf(a1, b1, __fmul_rn(a0, b0)));
}

// ---------------------------------------------------------------------------
// Per-pixel src patch stats (identical op order to reference) + (block 0,
// tid<4) camera-constant precompute folded in.
__global__ void __launch_bounds__(256)
init_kernel(const float* __restrict__ src,
            const float* __restrict__ Ks,
            const float* __restrict__ Rs,
            const float* __restrict__ Ts) {
    using namespace cfg;

    if (blockIdx.x == 0 && threadIdx.x < NVIEW) {
        int n = threadIdx.x;
        const float* Ki = Ks + n * 18;       // Ks[0,n,0] = K^-1
        const float* K  = Ks + n * 18 + 9;   // Ks[0,n,1] = K
        const float* R  = Rs + n * 9;
#pragma unroll
        for (int i = 0; i < 3; i++)
#pragma unroll
            for (int j = 0; j < 3; j++)
                g_PP[n][i * 3 + j] = dot3f(K[i * 3 + 0], R[0 * 3 + j],
                                           K[i * 3 + 1], R[1 * 3 + j],
                                           K[i * 3 + 2], R[2 * 3 + j]);
#pragma unroll
        for (int i = 0; i < 9; i++) g_K0[n][i] = Ki[i];
#pragma unroll
        for (int i = 0; i < 3; i++) g_T[n][i] = Ts[n * 3 + i];
    }

    int pix = blockIdx.x * blockDim.x + threadIdx.x;
    if (pix >= HW) return;
    int h = pix / W;
    int w = pix - h * W;

    float sp[PS];
    float ssum = 0.f;
#pragma unroll
    for (int p = 0; p < PS; p++) {
        int hh = h + p / 5 - 2, ww = w + p % 5 - 2;
        float v = 0.f;
        if (hh >= 0 && hh < H && ww >= 0 && ww < W) v = src[hh * W + ww];
        sp[p] = v;
        ssum = __fadd_rn(ssum, v);
    }
    float smean = __fdiv_rn(ssum, 25.f);
    float svar = 0.f;
#pragma unroll
    for (int p = 0; p < PS; p++) {
        float scv = __fsub_rn(sp[p], smean);
        svar = __fadd_rn(svar, __fmul_rn(scv, scv));
    }
    g_smean[pix] = smean;
    g_svar[pix]  = __fdiv_rn(svar, 25.f);
}

// ---------------------------------------------------------------------------
// One thread per (pixel, depth tap d [grid.y], view n [grid.z]).
__global__ void __launch_bounds__(256)
ncc_view_kernel(const float* __restrict__ src,
                const float* __restrict__ dst,
                const float* __restrict__ depth,
                const float* __restrict__ norm) {
    using namespace cfg;
    const int pix = blockIdx.x * blockDim.x + threadIdx.x;
    if (pix >= HW) return;
    const int d = blockIdx.y;
    const int n = blockIdx.z;
    const int h = pix / W;
    const int w = pix - h * W;

    float* vs_out = reinterpret_cast<float*>(&g_vs4[d * HW + pix]) + n;
    unsigned char* mb_out =
        reinterpret_cast<unsigned char*>(&g_mb4[d * HW + pix]) + n;

    const int pd = perm_d(d);
    const int pi = pd / 3 - 1;
    const int pj = pd % 3 - 1;

    // dilated depth tap (zero-padded)
    int hd = h + DIL * pi, wd = w + DIL * pj;
    float dp = 0.f;
    if (hd >= 0 && hd < H && wd >= 0 && wd < W) dp = depth[hd * W + wd];

    // normal tap (dilation 1, zero-padded)
    int hn = h + pi, wn = w + pj;
    float nv0 = 0.f, nv1 = 0.f, nv2 = 0.f;
    if (hn >= 0 && hn < H && wn >= 0 && wn < W) {
        int o = hn * W + wn;
        nv0 = norm[o];
        nv1 = norm[HW + o];
        nv2 = norm[2 * HW + o];
    }
    bool valid_dn = (dp > 0.f) && (nv2 < 0.f);
    bool interior = (h >= 2) && (h < H - 2) && (w >= 2) && (w < W - 2);

    if (!interior || !valid_dn) {   // any src tap OOB / invalid -> mall=false
        *vs_out = THR;
        *mb_out = 0;
        return;
    }

    const float dsafe = dp;  // dp > 0 here

    // m = I - (T_i * n_j) / dsafe  (entry-wise IEEE ops)
    float mM[9];
#pragma unroll
    for (int i = 0; i < 3; i++) {
        float Ti = g_T[n][i];
        float q0 = __fdiv_rn(__fmul_rn(Ti, nv0), dsafe);
        float q1 = __fdiv_rn(__fmul_rn(Ti, nv1), dsafe);
        float q2 = __fdiv_rn(__fmul_rn(Ti, nv2), dsafe);
        mM[i * 3 + 0] = __fsub_rn((i == 0) ? 1.f : 0.f, q0);
        mM[i * 3 + 1] = __fsub_rn((i == 1) ? 1.f : 0.f, q1);
        mM[i * 3 + 2] = __fsub_rn((i == 2) ? 1.f : 0.f, q2);
    }
    // tmp = PP @ m ; Hm = tmp @ K0  (mul+add chains)
    float tmp[9], Hm[9];
#pragma unroll
    for (int i = 0; i < 3; i++)
#pragma unroll
        for (int k = 0; k < 3; k++)
            tmp[i * 3 + k] = dot3m(g_PP[n][i * 3 + 0], mM[0 * 3 + k],
                                   g_PP[n][i * 3 + 1], mM[1 * 3 + k],
                                   g_PP[n][i * 3 + 2], mM[2 * 3 + k]);
#pragma unroll
    for (int i = 0; i < 3; i++)
#pragma unroll
        for (int l = 0; l < 3; l++)
            Hm[i * 3 + l] = dot3m(tmp[i * 3 + 0], g_K0[n][0 * 3 + l],
                                  tmp[i * 3 + 1], g_K0[n][1 * 3 + l],
                                  tmp[i * 3 + 2], g_K0[n][2 * 3 + l]);

    const float* dstn = dst + n * HW;
    const float fw = (float)w, fh = (float)h;
    float samp[PS];
    bool mall = true;
    float dsum = 0.f;

#pragma unroll
    for (int p = 0; p < PS; p++) {
        float cy = fh + (float)(p / 5 - 2);
        float cx = fw + (float)(p % 5 - 2);
        float X0 = dot3f(Hm[0], cx, Hm[1], cy, Hm[2], 1.f);
        float X1 = dot3f(Hm[3], cx, Hm[4], cy, Hm[5], 1.f);
        float z  = dot3f(Hm[6], cx, Hm[7], cy, Hm[8], 1.f);
        if (!(z > 0.f)) { mall = false; break; }  // divide results unused
        float xw = __fdiv_rn(X0, z);
        float yw = __fdiv_rn(X1, z);
        bool ok = (xw > 0.f) && (xw < (float)(W - 1)) &&
                  (yw > 0.f) && (yw < (float)(H - 1));
        if (!ok) { mall = false; break; }   // rest of this view unused
        float s = dstn[(int)yw * W + (int)xw];
        samp[p] = s;
        dsum = __fadd_rn(dsum, s);
    }

    if (!mall) {
        *vs_out = THR;
        *mb_out = 0;
        return;
    }

    // NCC: stats reloaded (bit-exact), cross reads src directly (interior)
    const float smean = g_smean[pix];
    const float svar  = g_svar[pix];
    float dmean = __fdiv_rn(dsum, 25.f);
    float dvar = 0.f, cross = 0.f;
    const float* srow = src + (h - 2) * W + (w - 2);
#pragma unroll
    for (int p = 0; p < PS; p++) {
        float dc = __fsub_rn(samp[p], dmean);
        dvar  = __fadd_rn(dvar,  __fmul_rn(dc, dc));
        float scv = __fsub_rn(srow[(p / 5) * W + (p % 5)], smean);
        cross = __fadd_rn(cross, __fmul_rn(scv, dc));
    }
    dvar  = __fdiv_rn(dvar, 25.f);
    cross = __fdiv_rn(cross, 25.f);
    float prod = __fmul_rn(svar, dvar);
    *vs_out = (prod > 0.f) ? __fdiv_rn(cross, __fsqrt_rn(prod)) : THR;
    *mb_out = 1;
}

// ---------------------------------------------------------------------------
// Final: per-pixel view combine (sequential sum, identical order), argmax
// over 9 depth taps (strict >, first-max), output assembly.
__global__ void __launch_bounds__(128)
ncc_final_kernel(const float* __restrict__ depth,
                 const float* __restrict__ norm,
                 float* __restrict__ out) {
    using namespace cfg;
    int pix = blockIdx.x * blockDim.x + threadIdx.x;
    if (pix >= HW) return;

    float best = -1e30f;
    int bd = 0;
    bool bmany = false;
#pragma unroll
    for (int dd = 0; dd < DS; dd++) {
        float4 v = g_vs4[dd * HW + pix];
        bool many = g_mb4[dd * HW + pix] != 0u;
        float ssc = __fadd_rn(__fadd_rn(__fadd_rn(v.x, v.y), v.z), v.w);
        float score = many ? __fdiv_rn(ssc, 4.f) : THR;
        if (score > best) { best = score; bd = dd; bmany = many; }
    }

    int h = pix / W;
    int w = pix - h * W;
    int pd = perm_d(bd);
    int pi = pd / 3 - 1;
    int pj = pd % 3 - 1;

    int hd = h + DIL * pi, wd = w + DIL * pj;
    float dp = 0.f;
    if (hd >= 0 && hd < H && wd >= 0 && wd < W) dp = depth[hd * W + wd];

    int hn = h + pi, wn = w + pj;
    float nx = 0.f, ny = 0.f, nz = 0.f;
    if (hn >= 0 && hn < H && wn >= 0 && wn < W) {
        int o = hn * W + wn;
        nx = norm[o];
        ny = norm[HW + o];
        nz = norm[2 * HW + o];
    }

    out[pix]          = __fsub_rn(1.f, best);
    out[HW + pix]     = dp;
    out[2 * HW + pix] = nx;
    out[3 * HW + pix] = ny;
    out[4 * HW + pix] = nz;
    out[5 * HW + pix] = bmany ? 1.f : 0.f;
}

// ---------------------------------------------------------------------------
extern "C" void kernel_launch(void* const* d_in, const int* in_sizes, int n_in,
                              void* d_out, int out_size) {
    const float* src   = (const float*)d_in[0];
    const float* dst   = (const float*)d_in[1];
    const float* Ks    = (const float*)d_in[2];
    const float* Rs    = (const float*)d_in[3];
    const float* Ts    = (const float*)d_in[4];
    const float* depth = (const float*)d_in[5];
    const float* norm  = (const float*)d_in[6];
    float* out = (float*)d_out;

    init_kernel<<<(cfg::HW + 255) / 256, 256>>>(src, Ks, Rs, Ts);
    dim3 grid((cfg::HW + 255) / 256, cfg::DS, cfg::NVIEW);
    ncc_view_kernel<<<grid, 256>>>(src, dst, depth, norm);
    ncc_final_kernel<<<(cfg::HW + 127) / 128, 128>>>(depth, norm, out);
}